// round 5
// baseline (speedup 1.0000x reference)
#include <cuda_runtime.h>
#include <cuda_fp16.h>
#include <cstdint>

// ============================================================================
// out[8192,2048] = x[8192,2048] @ W[2048,2048]^T + b   (fp32 in/out)
//
// fp16 mma.sync.m16n8k16, fp32 accum (tcgen05.ld rejected by plain sm_103
// ptxas). rel_err ~2e-4 vs 1e-3 threshold.
//
// R5 vs R4 (200.4us, GEMM 176.9us, tensor=64%):
//  - split-K=2 (grid z), RED.F32 epilogue, out pre-initialized with bias
//    in the prep kernel => 2048 CTAs, 6.9 waves, tail loss 13.5% -> ~2%
//  - manual k16 software pipeline (ping-pong fragments): LDSM k16+1 issued
//    before MMA k16 -> removes per-k16 tensor-pipe hole
//  - bias out of mainloop; hoisted cp.async/ldsm addressing (no per-iter
//    modulo, swz distributes over row-block strides)
// ============================================================================

#define DIM      2048
#define M_TOTAL  8192
#define KSPLIT   2
#define KHALF    (DIM / KSPLIT)      // 1024
#define BM       128
#define BN       128
#define BK       64
#define THREADS  256
#define STAGES   3
#define KITERS   (KHALF / BK)        // 16

__device__ __half g_Xh[(size_t)M_TOTAL * DIM];   // 32 MB
__device__ __half g_Wh[(size_t)DIM * DIM];       //  8 MB

#define A_BYTES     16384
#define STAGE_BYTES 32768
#define SMEM_BYTES  (STAGES * STAGE_BYTES)       // 98304

// ---------------------------------------------------------------------------
__device__ __forceinline__ uint32_t smem_u32(const void* p) {
    uint32_t a;
    asm("{ .reg .u64 t; cvta.to.shared.u64 t, %1; cvt.u32.u64 %0, t; }"
        : "=r"(a) : "l"(p));
    return a;
}
__device__ __forceinline__ uint32_t swz(uint32_t b) {   // SW128
    return b ^ ((b >> 3) & 0x70);
}
__device__ __forceinline__ void cp16(uint32_t dst, const void* src) {
    asm volatile("cp.async.cg.shared.global [%0], [%1], 16;"
                 :: "r"(dst), "l"(src));
}
#define CP_COMMIT() asm volatile("cp.async.commit_group;" ::: "memory")
#define CP_WAIT()   asm volatile("cp.async.wait_group %0;" :: "n"(STAGES - 2) : "memory")

#define LDSM4(r0, r1, r2, r3, addr) \
    asm volatile("ldmatrix.sync.aligned.m8n8.x4.shared.b16 {%0,%1,%2,%3}, [%4];" \
                 : "=r"(r0), "=r"(r1), "=r"(r2), "=r"(r3) : "r"(addr))

#define MMA16816(c0, c1, c2, c3, a0, a1, a2, a3, b0, b1) \
    asm volatile("mma.sync.aligned.m16n8k16.row.col.f32.f16.f16.f32 " \
                 "{%0,%1,%2,%3}, {%4,%5,%6,%7}, {%8,%9}, {%0,%1,%2,%3};" \
                 : "+f"(c0), "+f"(c1), "+f"(c2), "+f"(c3) \
                 : "r"(a0), "r"(a1), "r"(a2), "r"(a3), "r"(b0), "r"(b1))

__device__ __forceinline__ void redf(float* p, float v) {
    asm volatile("red.global.add.f32 [%0], %1;" :: "l"(p), "f"(v) : "memory");
}

// ============================================================================
// prep: fp32->fp16 convert (x, W) + out := bias broadcast, one launch
// ============================================================================
#define NX4 ((M_TOTAL * DIM) / 4)    // 4,194,304
#define NW4 ((DIM * DIM) / 4)        // 1,048,576
#define NO4 ((M_TOTAL * DIM) / 4)    // 4,194,304
#define PREP_BLOCKS ((NX4 + NW4 + NO4) / 256)

__global__ void __launch_bounds__(256) prep_kernel(const float4* __restrict__ x,
                                                   const float4* __restrict__ W,
                                                   const float4* __restrict__ bias4,
                                                   float4* __restrict__ out4) {
    int i = blockIdx.x * 256 + threadIdx.x;
    if (i < NX4 + NW4) {
        const float4* src;  uint2* dst;  int j;
        if (i < NX4) { src = x; dst = reinterpret_cast<uint2*>(g_Xh); j = i; }
        else         { src = W; dst = reinterpret_cast<uint2*>(g_Wh); j = i - NX4; }
        float4 v = src[j];
        __half2 lo = __floats2half2_rn(v.x, v.y);
        __half2 hi = __floats2half2_rn(v.z, v.w);
        uint2 p;
        p.x = *reinterpret_cast<uint32_t*>(&lo);
        p.y = *reinterpret_cast<uint32_t*>(&hi);
        dst[j] = p;
    } else {
        int j = i - (NX4 + NW4);                 // out float4 index
        out4[j] = __ldg(&bias4[j & (DIM / 4 - 1)]);
    }
}

// ============================================================================
// GEMM half-K: 128x128 CTA tile, 8 warps (2Mx4N), warp tile 64x32,
// 3-stage cp.async, k16 software pipeline, RED.F32 epilogue, 2 CTAs/SM.
// ============================================================================
struct Frag { uint32_t a[4][4]; uint32_t b[2][4]; };

__device__ __forceinline__ void ldsm_frags(Frag& f, uint32_t aB, uint32_t bB,
                                           uint32_t a_base, uint32_t b_base, int k16) {
    const uint32_t kb = (uint32_t)(k16 * 32);
    #pragma unroll
    for (int mt = 0; mt < 4; mt++) {
        // +mt*16 rows = +mt*2048 bytes: bits >=11, outside swz window -> adds
        uint32_t off = swz(a_base + kb) + (uint32_t)(mt << 11);
        LDSM4(f.a[mt][0], f.a[mt][1], f.a[mt][2], f.a[mt][3], aB + off);
    }
    #pragma unroll
    for (int p = 0; p < 2; p++) {
        uint32_t off = swz(b_base + kb) + (uint32_t)(p << 11);
        LDSM4(f.b[p][0], f.b[p][1], f.b[p][2], f.b[p][3], bB + off);
    }
}

__device__ __forceinline__ void mma_frags(float c[4][4][4], const Frag& f) {
    #pragma unroll
    for (int mt = 0; mt < 4; mt++)
        #pragma unroll
        for (int nb = 0; nb < 4; nb++)
            MMA16816(c[mt][nb][0], c[mt][nb][1], c[mt][nb][2], c[mt][nb][3],
                     f.a[mt][0], f.a[mt][1], f.a[mt][2], f.a[mt][3],
                     f.b[nb >> 1][(nb & 1) * 2], f.b[nb >> 1][(nb & 1) * 2 + 1]);
}

__global__ void __launch_bounds__(THREADS, 2) gemm_fp16_kernel(float* __restrict__ out)
{
    extern __shared__ __align__(1024) char smem[];
    const uint32_t sbase = smem_u32(smem);
    const int tid  = threadIdx.x;
    const int lane = tid & 31;
    const int wid  = tid >> 5;
    const int warp_m = wid & 1;
    const int warp_n = wid >> 1;

    const int nBase = blockIdx.x * BN;
    const int mBase = blockIdx.y * BM;
    const int kBase = blockIdx.z * KHALF;

    // per-thread cp.async bases: row = tid>>3, col chunk = (tid&7)*8 halves
    const int ldr = tid >> 3;                 // 0..31
    const int ldc = (tid & 7) * 8;            // halves
    const __half* aSrc = g_Xh + (size_t)(mBase + ldr) * DIM + kBase + ldc;
    const __half* bSrc = g_Wh + (size_t)(nBase + ldr) * DIM + kBase + ldc;
    const uint32_t dOff = swz((uint32_t)(ldr * 128 + ldc * 2));  // +i*4096 adds

    float c[4][4][4];
    #pragma unroll
    for (int mt = 0; mt < 4; mt++)
        #pragma unroll
        for (int nb = 0; nb < 4; nb++)
            #pragma unroll
            for (int r = 0; r < 4; r++) c[mt][nb][r] = 0.0f;

    // prologue: stages 0,1
    #pragma unroll
    for (int s = 0; s < STAGES - 1; s++) {
        const uint32_t st = sbase + (uint32_t)s * STAGE_BYTES;
        #pragma unroll
        for (int i = 0; i < 4; i++)
            cp16(st + dOff + (uint32_t)(i << 12), aSrc + (size_t)(i * 32) * DIM + s * BK);
        #pragma unroll
        for (int i = 0; i < 4; i++)
            cp16(st + A_BYTES + dOff + (uint32_t)(i << 12), bSrc + (size_t)(i * 32) * DIM + s * BK);
        CP_COMMIT();
    }

    // ldmatrix in-tile base offsets (pre-swizzle args; swz applied per k16)
    const uint32_t a_base = (uint32_t)(((warp_m * 64 + (lane & 15)) << 7) + ((lane >> 4) << 4));
    const uint32_t b_base = (uint32_t)(((warp_n * 32 + ((lane >> 4) << 3) + (lane & 7)) << 7)
                                       + (((lane >> 3) & 1) << 4));

    uint32_t soff_r = 0;                       // stage being consumed
    uint32_t soff_w = 2 * STAGE_BYTES;         // stage being filled (it+2)
    Frag f0, f1;

    for (int it = 0; it < KITERS; ++it) {
        CP_WAIT();
        __syncthreads();

        const uint32_t aB = sbase + soff_r;
        const uint32_t bB = aB + A_BYTES;

        // start LDSM for k16=0 immediately (latency overlaps cp.async issue)
        ldsm_frags(f0, aB, bB, a_base, b_base, 0);

        if (it + STAGES - 1 < KITERS) {
            const uint32_t st = sbase + soff_w;
            const int kc = (it + STAGES - 1) * BK;
            #pragma unroll
            for (int i = 0; i < 4; i++)
                cp16(st + dOff + (uint32_t)(i << 12), aSrc + (size_t)(i * 32) * DIM + kc);
            #pragma unroll
            for (int i = 0; i < 4; i++)
                cp16(st + A_BYTES + dOff + (uint32_t)(i << 12), bSrc + (size_t)(i * 32) * DIM + kc);
        }
        CP_COMMIT();

        // software-pipelined k16: LDSM(k+1) issued before MMA(k)
        ldsm_frags(f1, aB, bB, a_base, b_base, 1);
        mma_frags(c, f0);
        ldsm_frags(f0, aB, bB, a_base, b_base, 2);
        mma_frags(c, f1);
        ldsm_frags(f1, aB, bB, a_base, b_base, 3);
        mma_frags(c, f0);
        mma_frags(c, f1);

        soff_r += STAGE_BYTES; if (soff_r == STAGES * STAGE_BYTES) soff_r = 0;
        soff_w += STAGE_BYTES; if (soff_w == STAGES * STAGE_BYTES) soff_w = 0;
    }

    // epilogue: RED-add partials into bias-preinitialized out
    const int m0 = mBase + warp_m * 64 + (lane >> 2);
    const int n0 = nBase + warp_n * 32 + (lane & 3) * 2;
    #pragma unroll
    for (int mt = 0; mt < 4; mt++) {
        #pragma unroll
        for (int nb = 0; nb < 4; nb++) {
            const int row = m0 + mt * 16;
            const int col = n0 + nb * 8;
            float* p0 = out + (size_t)row * DIM + col;
            float* p1 = out + (size_t)(row + 8) * DIM + col;
            redf(p0,     c[mt][nb][0]);
            redf(p0 + 1, c[mt][nb][1]);
            redf(p1,     c[mt][nb][2]);
            redf(p1 + 1, c[mt][nb][3]);
        }
    }
}

// ============================================================================
// kernel_launch — graph-capturable, allocation-free
// ============================================================================
extern "C" void kernel_launch(void* const* d_in, const int* in_sizes, int n_in,
                              void* d_out, int out_size) {
    const float* x = (const float*)d_in[0];
    const float* W = (const float*)d_in[1];
    const float* b = (const float*)d_in[2];
    float* out = (float*)d_out;
    (void)in_sizes; (void)n_in; (void)out_size;

    prep_kernel<<<PREP_BLOCKS, 256>>>((const float4*)x, (const float4*)W,
                                      (const float4*)b, (float4*)out);

    cudaFuncSetAttribute(gemm_fp16_kernel,
                         cudaFuncAttributeMaxDynamicSharedMemorySize, SMEM_BYTES);
    dim3 grid(DIM / BN, M_TOTAL / BM, KSPLIT);   // (16, 64, 2) = 2048 CTAs
    gemm_fp16_kernel<<<grid, THREADS, SMEM_BYTES>>>(out);
}

// round 6
// speedup vs baseline: 1.0310x; 1.0310x over previous
#include <cuda_runtime.h>
#include <cuda_fp16.h>
#include <cstdint>

// ============================================================================
// out[8192,2048] = x[8192,2048] @ W[2048,2048]^T + b   (fp32 in/out)
//
// fp16 mma.sync.m16n8k16, fp32 accum (tcgen05.ld rejected by plain sm_103
// ptxas). rel_err 2.06e-4 vs 1e-3 threshold.
//
// R6 vs R5 (205.3us regression) and R4 (200.4us best):
//  - REVERT split-K + RED + out-preinit (cost ~12us overhead, gained 3)
//  - KEEP R5 mainloop: k16 software pipeline, hoisted addressing
//  - NEW: cp.async issue interleaved into k16 phases (no LSU burst at iter
//    start colliding with the first LDSMs)
// Measured invariant: tensor busy ~113us = HMMA floor; chasing duty cycle.
// ============================================================================

#define DIM      2048
#define M_TOTAL  8192
#define BM       128
#define BN       128
#define BK       64
#define THREADS  256
#define STAGES   3
#define KITERS   (DIM / BK)          // 32

__device__ __half g_Xh[(size_t)M_TOTAL * DIM];   // 32 MB
__device__ __half g_Wh[(size_t)DIM * DIM];       //  8 MB

#define A_BYTES     16384
#define STAGE_BYTES 32768
#define SMEM_BYTES  (STAGES * STAGE_BYTES)       // 98304

// ---------------------------------------------------------------------------
__device__ __forceinline__ uint32_t smem_u32(const void* p) {
    uint32_t a;
    asm("{ .reg .u64 t; cvta.to.shared.u64 t, %1; cvt.u32.u64 %0, t; }"
        : "=r"(a) : "l"(p));
    return a;
}
__device__ __forceinline__ uint32_t swz(uint32_t b) {   // SW128
    return b ^ ((b >> 3) & 0x70);
}
__device__ __forceinline__ void cp16(uint32_t dst, const void* src) {
    asm volatile("cp.async.cg.shared.global [%0], [%1], 16;"
                 :: "r"(dst), "l"(src));
}
#define CP_COMMIT() asm volatile("cp.async.commit_group;" ::: "memory")
#define CP_WAIT()   asm volatile("cp.async.wait_group %0;" :: "n"(STAGES - 2) : "memory")

#define LDSM4(r0, r1, r2, r3, addr) \
    asm volatile("ldmatrix.sync.aligned.m8n8.x4.shared.b16 {%0,%1,%2,%3}, [%4];" \
                 : "=r"(r0), "=r"(r1), "=r"(r2), "=r"(r3) : "r"(addr))

#define MMA16816(c0, c1, c2, c3, a0, a1, a2, a3, b0, b1) \
    asm volatile("mma.sync.aligned.m16n8k16.row.col.f32.f16.f16.f32 " \
                 "{%0,%1,%2,%3}, {%4,%5,%6,%7}, {%8,%9}, {%0,%1,%2,%3};" \
                 : "+f"(c0), "+f"(c1), "+f"(c2), "+f"(c3) \
                 : "r"(a0), "r"(a1), "r"(a2), "r"(a3), "r"(b0), "r"(b1))

// ============================================================================
// prep: fp32 -> fp16 convert (x and W in one launch)
// ============================================================================
#define NX4 ((M_TOTAL * DIM) / 4)    // 4,194,304
#define NW4 ((DIM * DIM) / 4)        // 1,048,576

__global__ void __launch_bounds__(256) conv_kernel(const float4* __restrict__ x,
                                                   const float4* __restrict__ W) {
    int i = blockIdx.x * 256 + threadIdx.x;
    const float4* src;
    uint2* dst;
    int j;
    if (i < NX4) { src = x; dst = reinterpret_cast<uint2*>(g_Xh); j = i; }
    else         { src = W; dst = reinterpret_cast<uint2*>(g_Wh); j = i - NX4; }
    float4 v = src[j];
    __half2 lo = __floats2half2_rn(v.x, v.y);
    __half2 hi = __floats2half2_rn(v.z, v.w);
    uint2 p;
    p.x = *reinterpret_cast<uint32_t*>(&lo);
    p.y = *reinterpret_cast<uint32_t*>(&hi);
    dst[j] = p;
}

// ============================================================================
// GEMM: 128x128 CTA tile, 8 warps (2Mx4N), warp tile 64x32, 3-stage cp.async,
// k16 software pipeline with interleaved cp issue, 2 CTAs/SM, direct epilogue.
// ============================================================================
struct Frag { uint32_t a[4][4]; uint32_t b[2][4]; };

__device__ __forceinline__ void ldsm_frags(Frag& f, uint32_t aB, uint32_t bB,
                                           uint32_t a_base, uint32_t b_base, int k16) {
    const uint32_t kb = (uint32_t)(k16 * 32);
    #pragma unroll
    for (int mt = 0; mt < 4; mt++) {
        uint32_t off = swz(a_base + kb) + (uint32_t)(mt << 11);
        LDSM4(f.a[mt][0], f.a[mt][1], f.a[mt][2], f.a[mt][3], aB + off);
    }
    #pragma unroll
    for (int p = 0; p < 2; p++) {
        uint32_t off = swz(b_base + kb) + (uint32_t)(p << 11);
        LDSM4(f.b[p][0], f.b[p][1], f.b[p][2], f.b[p][3], bB + off);
    }
}

__device__ __forceinline__ void mma_frags(float c[4][4][4], const Frag& f) {
    #pragma unroll
    for (int mt = 0; mt < 4; mt++)
        #pragma unroll
        for (int nb = 0; nb < 4; nb++)
            MMA16816(c[mt][nb][0], c[mt][nb][1], c[mt][nb][2], c[mt][nb][3],
                     f.a[mt][0], f.a[mt][1], f.a[mt][2], f.a[mt][3],
                     f.b[nb >> 1][(nb & 1) * 2], f.b[nb >> 1][(nb & 1) * 2 + 1]);
}

__global__ void __launch_bounds__(THREADS, 2) gemm_fp16_kernel(
    float* __restrict__ out, const float* __restrict__ bias)
{
    extern __shared__ __align__(1024) char smem[];
    const uint32_t sbase = smem_u32(smem);
    const int tid  = threadIdx.x;
    const int lane = tid & 31;
    const int wid  = tid >> 5;
    const int warp_m = wid & 1;
    const int warp_n = wid >> 1;

    const int nBase = blockIdx.x * BN;
    const int mBase = blockIdx.y * BM;

    // bias per thread (constant across mt)
    const int n0 = nBase + warp_n * 32 + (lane & 3) * 2;
    float2 bb[4];
    #pragma unroll
    for (int nb = 0; nb < 4; nb++)
        bb[nb] = __ldg(reinterpret_cast<const float2*>(bias + n0 + nb * 8));

    // per-thread cp.async bases
    const int ldr = tid >> 3;                 // 0..31
    const int ldc = (tid & 7) * 8;            // halves
    const __half* aSrc = g_Xh + (size_t)(mBase + ldr) * DIM + ldc;
    const __half* bSrc = g_Wh + (size_t)(nBase + ldr) * DIM + ldc;
    const uint32_t dOff = swz((uint32_t)(ldr * 128 + ldc * 2));

    float c[4][4][4];
    #pragma unroll
    for (int mt = 0; mt < 4; mt++)
        #pragma unroll
        for (int nb = 0; nb < 4; nb++)
            #pragma unroll
            for (int r = 0; r < 4; r++) c[mt][nb][r] = 0.0f;

    // prologue: stages 0,1
    #pragma unroll
    for (int s = 0; s < STAGES - 1; s++) {
        const uint32_t st = sbase + (uint32_t)s * STAGE_BYTES;
        #pragma unroll
        for (int i = 0; i < 4; i++)
            cp16(st + dOff + (uint32_t)(i << 12), aSrc + (size_t)(i * 32) * DIM + s * BK);
        #pragma unroll
        for (int i = 0; i < 4; i++)
            cp16(st + A_BYTES + dOff + (uint32_t)(i << 12), bSrc + (size_t)(i * 32) * DIM + s * BK);
        CP_COMMIT();
    }

    const uint32_t a_base = (uint32_t)(((warp_m * 64 + (lane & 15)) << 7) + ((lane >> 4) << 4));
    const uint32_t b_base = (uint32_t)(((warp_n * 32 + ((lane >> 4) << 3) + (lane & 7)) << 7)
                                       + (((lane >> 3) & 1) << 4));

    uint32_t soff_r = 0;
    uint32_t soff_w = 2 * STAGE_BYTES;
    Frag f0, f1;

    for (int it = 0; it < KITERS; ++it) {
        CP_WAIT();
        __syncthreads();

        const uint32_t aB = sbase + soff_r;
        const uint32_t bB = aB + A_BYTES;
        const bool doIssue = (it + STAGES - 1 < KITERS);
        const uint32_t st = sbase + soff_w;
        const int kc = (it + STAGES - 1) * BK;

        // k16 software pipeline with cp.async spread across phases
        ldsm_frags(f0, aB, bB, a_base, b_base, 0);
        if (doIssue) {
            cp16(st + dOff,                    aSrc + kc);
            cp16(st + dOff + (1u << 12),       aSrc + (size_t)32 * DIM + kc);
        }
        ldsm_frags(f1, aB, bB, a_base, b_base, 1);
        if (doIssue) {
            cp16(st + dOff + (2u << 12),       aSrc + (size_t)64 * DIM + kc);
            cp16(st + dOff + (3u << 12),       aSrc + (size_t)96 * DIM + kc);
        }
        mma_frags(c, f0);
        ldsm_frags(f0, aB, bB, a_base, b_base, 2);
        if (doIssue) {
            cp16(st + A_BYTES + dOff,              bSrc + kc);
            cp16(st + A_BYTES + dOff + (1u << 12), bSrc + (size_t)32 * DIM + kc);
        }
        mma_frags(c, f1);
        ldsm_frags(f1, aB, bB, a_base, b_base, 3);
        if (doIssue) {
            cp16(st + A_BYTES + dOff + (2u << 12), bSrc + (size_t)64 * DIM + kc);
            cp16(st + A_BYTES + dOff + (3u << 12), bSrc + (size_t)96 * DIM + kc);
        }
        CP_COMMIT();
        mma_frags(c, f0);
        mma_frags(c, f1);

        soff_r += STAGE_BYTES; if (soff_r == STAGES * STAGE_BYTES) soff_r = 0;
        soff_w += STAGE_BYTES; if (soff_w == STAGES * STAGE_BYTES) soff_w = 0;
    }

    // epilogue: direct stores with bias (verified layout)
    const int m0 = mBase + warp_m * 64 + (lane >> 2);
    #pragma unroll
    for (int mt = 0; mt < 4; mt++) {
        #pragma unroll
        for (int nb = 0; nb < 4; nb++) {
            const int row = m0 + mt * 16;
            const int col = n0 + nb * 8;
            float2 v0, v1;
            v0.x = c[mt][nb][0] + bb[nb].x;  v0.y = c[mt][nb][1] + bb[nb].y;
            v1.x = c[mt][nb][2] + bb[nb].x;  v1.y = c[mt][nb][3] + bb[nb].y;
            *reinterpret_cast<float2*>(out + (size_t)row * DIM + col) = v0;
            *reinterpret_cast<float2*>(out + (size_t)(row + 8) * DIM + col) = v1;
        }
    }
}

// ============================================================================
// kernel_launch — graph-capturable, allocation-free
// ============================================================================
extern "C" void kernel_launch(void* const* d_in, const int* in_sizes, int n_in,
                              void* d_out, int out_size) {
    const float* x = (const float*)d_in[0];
    const float* W = (const float*)d_in[1];
    const float* b = (const float*)d_in[2];
    float* out = (float*)d_out;
    (void)in_sizes; (void)n_in; (void)out_size;

    conv_kernel<<<(NX4 + NW4) / 256, 256>>>((const float4*)x, (const float4*)W);

    cudaFuncSetAttribute(gemm_fp16_kernel,
                         cudaFuncAttributeMaxDynamicSharedMemorySize, SMEM_BYTES);
    dim3 grid(DIM / BN, M_TOTAL / BM);        // (16, 64) = 1024 CTAs
    gemm_fp16_kernel<<<grid, THREADS, SMEM_BYTES>>>(out, b);
}

// round 7
// speedup vs baseline: 1.1625x; 1.1276x over previous
#include <cuda_runtime.h>
#include <cuda_fp16.h>
#include <cstdint>

// ============================================================================
// out[8192,2048] = x[8192,2048] @ W[2048,2048]^T + b   (fp32 in/out)
//
// fp16 mma.sync.m16n8k16, fp32 accum (tcgen05.ld rejected by plain sm_103
// ptxas). rel_err 2.06e-4 vs 1e-3 threshold.
//
// R7 vs R6 (199.1us, GEMM 176.9us, tensor=64.8% pinned across 3 schedules):
//  Tensor busy 114us = rt~8 HMMA floor; elapsed/iter ~3150cyc vs 2050 work
//  => ~1100cyc/iter hole from __syncthreads lockstep + post-barrier LDSM herd.
//  - REPLACE __syncthreads + cp.async.wait_group with per-stage mbarrier
//    producer/consumer (full: cnt 256 via cp.async.mbarrier.arrive.noinc;
//    empty: cnt 8, warp arrives after its MMAs of the stage issued).
//  - Warps free-run with <=2-iter skew; crossbar load despreads.
// ============================================================================

#define DIM      2048
#define M_TOTAL  8192
#define BM       128
#define BN       128
#define BK       64
#define THREADS  256
#define STAGES   3
#define KITERS   (DIM / BK)          // 32

__device__ __half g_Xh[(size_t)M_TOTAL * DIM];   // 32 MB
__device__ __half g_Wh[(size_t)DIM * DIM];       //  8 MB

#define A_BYTES     16384
#define STAGE_BYTES 32768
#define TILES_BYTES (STAGES * STAGE_BYTES)       // 98304
#define SMEM_BYTES  (TILES_BYTES + 64)           // + mbarriers

// ---------------------------------------------------------------------------
__device__ __forceinline__ uint32_t smem_u32(const void* p) {
    uint32_t a;
    asm("{ .reg .u64 t; cvta.to.shared.u64 t, %1; cvt.u32.u64 %0, t; }"
        : "=r"(a) : "l"(p));
    return a;
}
__device__ __forceinline__ uint32_t swz(uint32_t b) {   // SW128
    return b ^ ((b >> 3) & 0x70);
}
__device__ __forceinline__ void cp16(uint32_t dst, const void* src) {
    asm volatile("cp.async.cg.shared.global [%0], [%1], 16;"
                 :: "r"(dst), "l"(src));
}
__device__ __forceinline__ void cp_arrive(uint32_t mbar) {
    asm volatile("cp.async.mbarrier.arrive.noinc.shared::cta.b64 [%0];"
                 :: "r"(mbar) : "memory");
}
__device__ __forceinline__ void mbar_init(uint32_t mbar, uint32_t cnt) {
    asm volatile("mbarrier.init.shared.b64 [%0], %1;" :: "r"(mbar), "r"(cnt) : "memory");
}
__device__ __forceinline__ void mbar_arrive(uint32_t mbar) {
    asm volatile("mbarrier.arrive.shared::cta.b64 _, [%0];" :: "r"(mbar) : "memory");
}
__device__ __forceinline__ void mbar_wait(uint32_t mbar, uint32_t parity) {
    asm volatile(
        "{\n\t.reg .pred P;\n\t"
        "WAITLP_%=:\n\t"
        "mbarrier.try_wait.parity.acquire.cta.shared::cta.b64 P, [%0], %1, 0x989680;\n\t"
        "@!P bra WAITLP_%=;\n\t}"
        :: "r"(mbar), "r"(parity) : "memory");
}

#define LDSM4(r0, r1, r2, r3, addr) \
    asm volatile("ldmatrix.sync.aligned.m8n8.x4.shared.b16 {%0,%1,%2,%3}, [%4];" \
                 : "=r"(r0), "=r"(r1), "=r"(r2), "=r"(r3) : "r"(addr))

#define MMA16816(c0, c1, c2, c3, a0, a1, a2, a3, b0, b1) \
    asm volatile("mma.sync.aligned.m16n8k16.row.col.f32.f16.f16.f32 " \
                 "{%0,%1,%2,%3}, {%4,%5,%6,%7}, {%8,%9}, {%0,%1,%2,%3};" \
                 : "+f"(c0), "+f"(c1), "+f"(c2), "+f"(c3) \
                 : "r"(a0), "r"(a1), "r"(a2), "r"(a3), "r"(b0), "r"(b1))

// ============================================================================
// prep: fp32 -> fp16 convert (x and W in one launch)
// ============================================================================
#define NX4 ((M_TOTAL * DIM) / 4)    // 4,194,304
#define NW4 ((DIM * DIM) / 4)        // 1,048,576

__global__ void __launch_bounds__(256) conv_kernel(const float4* __restrict__ x,
                                                   const float4* __restrict__ W) {
    int i = blockIdx.x * 256 + threadIdx.x;
    const float4* src;
    uint2* dst;
    int j;
    if (i < NX4) { src = x; dst = reinterpret_cast<uint2*>(g_Xh); j = i; }
    else         { src = W; dst = reinterpret_cast<uint2*>(g_Wh); j = i - NX4; }
    float4 v = src[j];
    __half2 lo = __floats2half2_rn(v.x, v.y);
    __half2 hi = __floats2half2_rn(v.z, v.w);
    uint2 p;
    p.x = *reinterpret_cast<uint32_t*>(&lo);
    p.y = *reinterpret_cast<uint32_t*>(&hi);
    dst[j] = p;
}

// ============================================================================
// GEMM: 128x128 CTA tile, 8 warps (2Mx4N), warp tile 64x32, 3-stage pipeline
// on mbarriers (no __syncthreads in mainloop), 2 CTAs/SM, direct epilogue.
// ============================================================================
struct Frag { uint32_t a[4][4]; uint32_t b[2][4]; };

__device__ __forceinline__ void ldsm_frags(Frag& f, uint32_t aB, uint32_t bB,
                                           uint32_t a_base, uint32_t b_base, int k16) {
    const uint32_t kb = (uint32_t)(k16 * 32);
    #pragma unroll
    for (int mt = 0; mt < 4; mt++) {
        uint32_t off = swz(a_base + kb) + (uint32_t)(mt << 11);
        LDSM4(f.a[mt][0], f.a[mt][1], f.a[mt][2], f.a[mt][3], aB + off);
    }
    #pragma unroll
    for (int p = 0; p < 2; p++) {
        uint32_t off = swz(b_base + kb) + (uint32_t)(p << 11);
        LDSM4(f.b[p][0], f.b[p][1], f.b[p][2], f.b[p][3], bB + off);
    }
}

__device__ __forceinline__ void mma_frags(float c[4][4][4], const Frag& f) {
    #pragma unroll
    for (int mt = 0; mt < 4; mt++)
        #pragma unroll
        for (int nb = 0; nb < 4; nb++)
            MMA16816(c[mt][nb][0], c[mt][nb][1], c[mt][nb][2], c[mt][nb][3],
                     f.a[mt][0], f.a[mt][1], f.a[mt][2], f.a[mt][3],
                     f.b[nb >> 1][(nb & 1) * 2], f.b[nb >> 1][(nb & 1) * 2 + 1]);
}

__global__ void __launch_bounds__(THREADS, 2) gemm_fp16_kernel(
    float* __restrict__ out, const float* __restrict__ bias)
{
    extern __shared__ __align__(1024) char smem[];
    const uint32_t sbase = smem_u32(smem);
    const int tid  = threadIdx.x;
    const int lane = tid & 31;
    const int wid  = tid >> 5;
    const int warp_m = wid & 1;
    const int warp_n = wid >> 1;

    const int nBase = blockIdx.x * BN;
    const int mBase = blockIdx.y * BM;

    const uint32_t fullb  = sbase + TILES_BYTES;        // 3 x 8B
    const uint32_t emptyb = sbase + TILES_BYTES + 24;   // 3 x 8B

    if (tid == 0) {
        #pragma unroll
        for (int s = 0; s < STAGES; s++) {
            mbar_init(fullb  + s * 8, THREADS);   // each thread cp-arrives
            mbar_init(emptyb + s * 8, 8);         // one arrive per warp
        }
        // pre-trip empty[2]: its first producer wait (it=0) must pass
        #pragma unroll
        for (int k = 0; k < 8; k++) mbar_arrive(emptyb + 2 * 8);
    }

    // bias per thread (constant across mt)
    const int n0 = nBase + warp_n * 32 + (lane & 3) * 2;
    float2 bb[4];
    #pragma unroll
    for (int nb = 0; nb < 4; nb++)
        bb[nb] = __ldg(reinterpret_cast<const float2*>(bias + n0 + nb * 8));

    // per-thread cp.async bases
    const int ldr = tid >> 3;                 // 0..31
    const int ldc = (tid & 7) * 8;            // halves
    const __half* aSrc = g_Xh + (size_t)(mBase + ldr) * DIM + ldc;
    const __half* bSrc = g_Wh + (size_t)(nBase + ldr) * DIM + ldc;
    const uint32_t dOff = swz((uint32_t)(ldr * 128 + ldc * 2));

    float c[4][4][4];
    #pragma unroll
    for (int mt = 0; mt < 4; mt++)
        #pragma unroll
        for (int nb = 0; nb < 4; nb++)
            #pragma unroll
            for (int r = 0; r < 4; r++) c[mt][nb][r] = 0.0f;

    __syncthreads();   // mbarrier init visible before any use

    // prologue: produce chunks 0,1 into buffers 0,1
    #pragma unroll
    for (int s = 0; s < 2; s++) {
        const uint32_t st = sbase + (uint32_t)s * STAGE_BYTES;
        #pragma unroll
        for (int i = 0; i < 4; i++)
            cp16(st + dOff + (uint32_t)(i << 12), aSrc + (size_t)(i * 32) * DIM + s * BK);
        #pragma unroll
        for (int i = 0; i < 4; i++)
            cp16(st + A_BYTES + dOff + (uint32_t)(i << 12), bSrc + (size_t)(i * 32) * DIM + s * BK);
        cp_arrive(fullb + s * 8);
    }

    const uint32_t a_base = (uint32_t)(((warp_m * 64 + (lane & 15)) << 7) + ((lane >> 4) << 4));
    const uint32_t b_base = (uint32_t)(((warp_n * 32 + ((lane >> 4) << 3) + (lane & 7)) << 7)
                                       + (((lane >> 3) & 1) << 4));

    uint32_t pf = 0, pe = 0;   // per-stage parity bitmasks (bit s)
    int s = 0;
    Frag f0, f1;

    for (int it = 0; it < KITERS; ++it) {
        // ---- consume chunk it from buffer s ----
        mbar_wait(fullb + s * 8, (pf >> s) & 1u);
        pf ^= (1u << s);

        const uint32_t aB = sbase + (uint32_t)s * STAGE_BYTES;
        const uint32_t bB = aB + A_BYTES;

        ldsm_frags(f0, aB, bB, a_base, b_base, 0);
        ldsm_frags(f1, aB, bB, a_base, b_base, 1);
        mma_frags(c, f0);
        ldsm_frags(f0, aB, bB, a_base, b_base, 2);
        mma_frags(c, f1);
        ldsm_frags(f1, aB, bB, a_base, b_base, 3);
        mma_frags(c, f0);
        mma_frags(c, f1);

        // MMAs issued => fragment regs valid => LDSM smem reads performed
        if (lane == 0) mbar_arrive(emptyb + s * 8);

        // ---- produce chunk it+2 into buffer sw = (it+2)%3 ----
        if (it + 2 < KITERS) {
            int sw = s + 2; if (sw >= STAGES) sw -= STAGES;
            mbar_wait(emptyb + sw * 8, (pe >> sw) & 1u);
            pe ^= (1u << sw);

            const uint32_t st = sbase + (uint32_t)sw * STAGE_BYTES;
            const int kc = (it + 2) * BK;
            #pragma unroll
            for (int i = 0; i < 4; i++)
                cp16(st + dOff + (uint32_t)(i << 12), aSrc + (size_t)(i * 32) * DIM + kc);
            #pragma unroll
            for (int i = 0; i < 4; i++)
                cp16(st + A_BYTES + dOff + (uint32_t)(i << 12), bSrc + (size_t)(i * 32) * DIM + kc);
            cp_arrive(fullb + sw * 8);
        }

        s++; if (s == STAGES) s = 0;
    }

    // epilogue: direct stores with bias (verified layout)
    const int m0 = mBase + warp_m * 64 + (lane >> 2);
    #pragma unroll
    for (int mt = 0; mt < 4; mt++) {
        #pragma unroll
        for (int nb = 0; nb < 4; nb++) {
            const int row = m0 + mt * 16;
            const int col = n0 + nb * 8;
            float2 v0, v1;
            v0.x = c[mt][nb][0] + bb[nb].x;  v0.y = c[mt][nb][1] + bb[nb].y;
            v1.x = c[mt][nb][2] + bb[nb].x;  v1.y = c[mt][nb][3] + bb[nb].y;
            *reinterpret_cast<float2*>(out + (size_t)row * DIM + col) = v0;
            *reinterpret_cast<float2*>(out + (size_t)(row + 8) * DIM + col) = v1;
        }
    }
}

// ============================================================================
// kernel_launch — graph-capturable, allocation-free
// ============================================================================
extern "C" void kernel_launch(void* const* d_in, const int* in_sizes, int n_in,
                              void* d_out, int out_size) {
    const float* x = (const float*)d_in[0];
    const float* W = (const float*)d_in[1];
    const float* b = (const float*)d_in[2];
    float* out = (float*)d_out;
    (void)in_sizes; (void)n_in; (void)out_size;

    conv_kernel<<<(NX4 + NW4) / 256, 256>>>((const float4*)x, (const float4*)W);

    cudaFuncSetAttribute(gemm_fp16_kernel,
                         cudaFuncAttributeMaxDynamicSharedMemorySize, SMEM_BYTES);
    dim3 grid(DIM / BN, M_TOTAL / BM);        // (16, 64) = 1024 CTAs
    gemm_fp16_kernel<<<grid, THREADS, SMEM_BYTES>>>(out, b);
}

// round 8
// speedup vs baseline: 1.1935x; 1.0266x over previous
#include <cuda_runtime.h>
#include <cuda_fp16.h>
#include <cstdint>

// ============================================================================
// out[8192,2048] = x[8192,2048] @ W[2048,2048]^T + b   (fp32 in/out)
//
// fp16 mma.sync.m16n8k16, fp32 accum (tcgen05.ld rejected by plain sm_103
// ptxas). rel_err 2.06e-4 vs 1e-3 threshold.
//
// R8 vs R7 (176.6us = GEMM 150.9 @ tensor 74.8% + prep 25.7):
//  - conv: 8 floats/thread (2x LDG.128 -> 1x STG.128), halves transactions
//    (R2 profile: 55% HBM, issue-bound on 8B stores)
//  - GEMM: producer block hoisted mid-pipeline (empty[sw] wait is for the
//    buffer consumed last iter -> nearly always open); empty-arrive stays
//    after the last MMA (correctness: proves all LDSM reads completed)
//  - mbarrier free-run protocol, 2 CTAs/SM, tile config: FROZEN (R7 win)
// ============================================================================

#define DIM      2048
#define M_TOTAL  8192
#define BM       128
#define BN       128
#define BK       64
#define THREADS  256
#define STAGES   3
#define KITERS   (DIM / BK)          // 32

__device__ __half g_Xh[(size_t)M_TOTAL * DIM];   // 32 MB
__device__ __half g_Wh[(size_t)DIM * DIM];       //  8 MB

#define A_BYTES     16384
#define STAGE_BYTES 32768
#define TILES_BYTES (STAGES * STAGE_BYTES)       // 98304
#define SMEM_BYTES  (TILES_BYTES + 64)           // + mbarriers

// ---------------------------------------------------------------------------
__device__ __forceinline__ uint32_t smem_u32(const void* p) {
    uint32_t a;
    asm("{ .reg .u64 t; cvta.to.shared.u64 t, %1; cvt.u32.u64 %0, t; }"
        : "=r"(a) : "l"(p));
    return a;
}
__device__ __forceinline__ uint32_t swz(uint32_t b) {   // SW128
    return b ^ ((b >> 3) & 0x70);
}
__device__ __forceinline__ void cp16(uint32_t dst, const void* src) {
    asm volatile("cp.async.cg.shared.global [%0], [%1], 16;"
                 :: "r"(dst), "l"(src));
}
__device__ __forceinline__ void cp_arrive(uint32_t mbar) {
    asm volatile("cp.async.mbarrier.arrive.noinc.shared::cta.b64 [%0];"
                 :: "r"(mbar) : "memory");
}
__device__ __forceinline__ void mbar_init(uint32_t mbar, uint32_t cnt) {
    asm volatile("mbarrier.init.shared.b64 [%0], %1;" :: "r"(mbar), "r"(cnt) : "memory");
}
__device__ __forceinline__ void mbar_arrive(uint32_t mbar) {
    asm volatile("mbarrier.arrive.shared::cta.b64 _, [%0];" :: "r"(mbar) : "memory");
}
__device__ __forceinline__ void mbar_wait(uint32_t mbar, uint32_t parity) {
    asm volatile(
        "{\n\t.reg .pred P;\n\t"
        "WAITLP_%=:\n\t"
        "mbarrier.try_wait.parity.acquire.cta.shared::cta.b64 P, [%0], %1, 0x989680;\n\t"
        "@!P bra WAITLP_%=;\n\t}"
        :: "r"(mbar), "r"(parity) : "memory");
}

#define LDSM4(r0, r1, r2, r3, addr) \
    asm volatile("ldmatrix.sync.aligned.m8n8.x4.shared.b16 {%0,%1,%2,%3}, [%4];" \
                 : "=r"(r0), "=r"(r1), "=r"(r2), "=r"(r3) : "r"(addr))

#define MMA16816(c0, c1, c2, c3, a0, a1, a2, a3, b0, b1) \
    asm volatile("mma.sync.aligned.m16n8k16.row.col.f32.f16.f16.f32 " \
                 "{%0,%1,%2,%3}, {%4,%5,%6,%7}, {%8,%9}, {%0,%1,%2,%3};" \
                 : "+f"(c0), "+f"(c1), "+f"(c2), "+f"(c3) \
                 : "r"(a0), "r"(a1), "r"(a2), "r"(a3), "r"(b0), "r"(b1))

// ============================================================================
// prep: fp32 -> fp16 convert, 8 floats per thread (2 LDG.128 -> 1 STG.128)
// ============================================================================
#define NX8 ((M_TOTAL * DIM) / 8)    // 2,097,152
#define NW8 ((DIM * DIM) / 8)        //   524,288

__device__ __forceinline__ uint4 pack8(float4 v0, float4 v1) {
    __half2 h0 = __floats2half2_rn(v0.x, v0.y);
    __half2 h1 = __floats2half2_rn(v0.z, v0.w);
    __half2 h2 = __floats2half2_rn(v1.x, v1.y);
    __half2 h3 = __floats2half2_rn(v1.z, v1.w);
    uint4 p;
    p.x = *reinterpret_cast<uint32_t*>(&h0);
    p.y = *reinterpret_cast<uint32_t*>(&h1);
    p.z = *reinterpret_cast<uint32_t*>(&h2);
    p.w = *reinterpret_cast<uint32_t*>(&h3);
    return p;
}

__global__ void __launch_bounds__(256) conv_kernel(const float4* __restrict__ x,
                                                   const float4* __restrict__ W) {
    int i = blockIdx.x * 256 + threadIdx.x;
    const float4* src;
    uint4* dst;
    int j;
    if (i < NX8) { src = x; dst = reinterpret_cast<uint4*>(g_Xh); j = i; }
    else         { src = W; dst = reinterpret_cast<uint4*>(g_Wh); j = i - NX8; }
    float4 v0 = src[2 * j];
    float4 v1 = src[2 * j + 1];
    dst[j] = pack8(v0, v1);
}

// ============================================================================
// GEMM: 128x128 CTA tile, 8 warps (2Mx4N), warp tile 64x32, 3-stage mbarrier
// producer/consumer pipeline (no __syncthreads in mainloop), 2 CTAs/SM.
// ============================================================================
struct Frag { uint32_t a[4][4]; uint32_t b[2][4]; };

__device__ __forceinline__ void ldsm_frags(Frag& f, uint32_t aB, uint32_t bB,
                                           uint32_t a_base, uint32_t b_base, int k16) {
    const uint32_t kb = (uint32_t)(k16 * 32);
    #pragma unroll
    for (int mt = 0; mt < 4; mt++) {
        uint32_t off = swz(a_base + kb) + (uint32_t)(mt << 11);
        LDSM4(f.a[mt][0], f.a[mt][1], f.a[mt][2], f.a[mt][3], aB + off);
    }
    #pragma unroll
    for (int p = 0; p < 2; p++) {
        uint32_t off = swz(b_base + kb) + (uint32_t)(p << 11);
        LDSM4(f.b[p][0], f.b[p][1], f.b[p][2], f.b[p][3], bB + off);
    }
}

__device__ __forceinline__ void mma_frags(float c[4][4][4], const Frag& f) {
    #pragma unroll
    for (int mt = 0; mt < 4; mt++)
        #pragma unroll
        for (int nb = 0; nb < 4; nb++)
            MMA16816(c[mt][nb][0], c[mt][nb][1], c[mt][nb][2], c[mt][nb][3],
                     f.a[mt][0], f.a[mt][1], f.a[mt][2], f.a[mt][3],
                     f.b[nb >> 1][(nb & 1) * 2], f.b[nb >> 1][(nb & 1) * 2 + 1]);
}

__global__ void __launch_bounds__(THREADS, 2) gemm_fp16_kernel(
    float* __restrict__ out, const float* __restrict__ bias)
{
    extern __shared__ __align__(1024) char smem[];
    const uint32_t sbase = smem_u32(smem);
    const int tid  = threadIdx.x;
    const int lane = tid & 31;
    const int wid  = tid >> 5;
    const int warp_m = wid & 1;
    const int warp_n = wid >> 1;

    const int nBase = blockIdx.x * BN;
    const int mBase = blockIdx.y * BM;

    const uint32_t fullb  = sbase + TILES_BYTES;        // 3 x 8B
    const uint32_t emptyb = sbase + TILES_BYTES + 24;   // 3 x 8B

    if (tid == 0) {
        #pragma unroll
        for (int s = 0; s < STAGES; s++) {
            mbar_init(fullb  + s * 8, THREADS);   // each thread cp-arrives
            mbar_init(emptyb + s * 8, 8);         // one arrive per warp
        }
        // pre-trip empty[2]: its first producer wait (it=0) must pass
        #pragma unroll
        for (int k = 0; k < 8; k++) mbar_arrive(emptyb + 2 * 8);
    }

    // bias per thread (constant across mt)
    const int n0 = nBase + warp_n * 32 + (lane & 3) * 2;
    float2 bb[4];
    #pragma unroll
    for (int nb = 0; nb < 4; nb++)
        bb[nb] = __ldg(reinterpret_cast<const float2*>(bias + n0 + nb * 8));

    // per-thread cp.async bases
    const int ldr = tid >> 3;                 // 0..31
    const int ldc = (tid & 7) * 8;            // halves
    const __half* aSrc = g_Xh + (size_t)(mBase + ldr) * DIM + ldc;
    const __half* bSrc = g_Wh + (size_t)(nBase + ldr) * DIM + ldc;
    const uint32_t dOff = swz((uint32_t)(ldr * 128 + ldc * 2));

    float c[4][4][4];
    #pragma unroll
    for (int mt = 0; mt < 4; mt++)
        #pragma unroll
        for (int nb = 0; nb < 4; nb++)
            #pragma unroll
            for (int r = 0; r < 4; r++) c[mt][nb][r] = 0.0f;

    __syncthreads();   // mbarrier init visible before any use

    // prologue: produce chunks 0,1 into buffers 0,1
    #pragma unroll
    for (int s = 0; s < 2; s++) {
        const uint32_t st = sbase + (uint32_t)s * STAGE_BYTES;
        #pragma unroll
        for (int i = 0; i < 4; i++)
            cp16(st + dOff + (uint32_t)(i << 12), aSrc + (size_t)(i * 32) * DIM + s * BK);
        #pragma unroll
        for (int i = 0; i < 4; i++)
            cp16(st + A_BYTES + dOff + (uint32_t)(i << 12), bSrc + (size_t)(i * 32) * DIM + s * BK);
        cp_arrive(fullb + s * 8);
    }

    const uint32_t a_base = (uint32_t)(((warp_m * 64 + (lane & 15)) << 7) + ((lane >> 4) << 4));
    const uint32_t b_base = (uint32_t)(((warp_n * 32 + ((lane >> 4) << 3) + (lane & 7)) << 7)
                                       + (((lane >> 3) & 1) << 4));

    uint32_t pf = 0, pe = 0;   // per-stage parity bitmasks (bit s)
    int s = 0;
    Frag f0, f1;

    for (int it = 0; it < KITERS; ++it) {
        // ---- consume chunk it from buffer s ----
        mbar_wait(fullb + s * 8, (pf >> s) & 1u);
        pf ^= (1u << s);

        const uint32_t aB = sbase + (uint32_t)s * STAGE_BYTES;
        const uint32_t bB = aB + A_BYTES;

        ldsm_frags(f0, aB, bB, a_base, b_base, 0);
        ldsm_frags(f1, aB, bB, a_base, b_base, 1);
        mma_frags(c, f0);

        // ---- produce chunk it+2 into buffer sw (hoisted mid-pipeline;
        //      empty[sw] was consumed at iter it-1 -> wait nearly always open)
        if (it + 2 < KITERS) {
            int sw = s + 2; if (sw >= STAGES) sw -= STAGES;
            mbar_wait(emptyb + sw * 8, (pe >> sw) & 1u);
            pe ^= (1u << sw);

            const uint32_t st = sbase + (uint32_t)sw * STAGE_BYTES;
            const int kc = (it + 2) * BK;
            #pragma unroll
            for (int i = 0; i < 4; i++)
                cp16(st + dOff + (uint32_t)(i << 12), aSrc + (size_t)(i * 32) * DIM + kc);
            #pragma unroll
            for (int i = 0; i < 4; i++)
                cp16(st + A_BYTES + dOff + (uint32_t)(i << 12), bSrc + (size_t)(i * 32) * DIM + kc);
            cp_arrive(fullb + sw * 8);
        }

        ldsm_frags(f0, aB, bB, a_base, b_base, 2);
        mma_frags(c, f1);
        ldsm_frags(f1, aB, bB, a_base, b_base, 3);
        mma_frags(c, f0);
        mma_frags(c, f1);

        // all MMAs issued => all LDSM reads of buffer s completed
        if (lane == 0) mbar_arrive(emptyb + s * 8);

        s++; if (s == STAGES) s = 0;
    }

    // epilogue: direct stores with bias (verified layout)
    const int m0 = mBase + warp_m * 64 + (lane >> 2);
    #pragma unroll
    for (int mt = 0; mt < 4; mt++) {
        #pragma unroll
        for (int nb = 0; nb < 4; nb++) {
            const int row = m0 + mt * 16;
            const int col = n0 + nb * 8;
            float2 v0, v1;
            v0.x = c[mt][nb][0] + bb[nb].x;  v0.y = c[mt][nb][1] + bb[nb].y;
            v1.x = c[mt][nb][2] + bb[nb].x;  v1.y = c[mt][nb][3] + bb[nb].y;
            *reinterpret_cast<float2*>(out + (size_t)row * DIM + col) = v0;
            *reinterpret_cast<float2*>(out + (size_t)(row + 8) * DIM + col) = v1;
        }
    }
}

// ============================================================================
// kernel_launch — graph-capturable, allocation-free
// ============================================================================
extern "C" void kernel_launch(void* const* d_in, const int* in_sizes, int n_in,
                              void* d_out, int out_size) {
    const float* x = (const float*)d_in[0];
    const float* W = (const float*)d_in[1];
    const float* b = (const float*)d_in[2];
    float* out = (float*)d_out;
    (void)in_sizes; (void)n_in; (void)out_size;

    conv_kernel<<<(NX8 + NW8) / 256, 256>>>((const float4*)x, (const float4*)W);

    cudaFuncSetAttribute(gemm_fp16_kernel,
                         cudaFuncAttributeMaxDynamicSharedMemorySize, SMEM_BYTES);
    dim3 grid(DIM / BN, M_TOTAL / BM);        // (16, 64) = 1024 CTAs
    gemm_fp16_kernel<<<grid, THREADS, SMEM_BYTES>>>(out, b);
}

// round 9
// speedup vs baseline: 1.2058x; 1.0103x over previous
#include <cuda_runtime.h>
#include <cuda_fp16.h>
#include <cstdint>

// ============================================================================
// out[8192,2048] = x[8192,2048] @ W[2048,2048]^T + b   (fp32 in/out)
//
// fp16 mma.sync.m16n8k16, fp32 accum (tcgen05.ld rejected by plain sm_103
// ptxas). rel_err 2.06e-4 vs 1e-3 threshold.
//
// R9 vs R8 (172.0us = GEMM 152.3 @ tensor 74.4% + conv 19.7):
//  GEMM idle = ~20us wave tail (1024 CTAs / 296 slots = 3.46 waves) + polls.
//  - TAIL-ONLY split-K: tiles 0..887 (3 full waves) unchanged (full K,
//    direct store+bias). Tiles 888..1023 (the partial 4th wave) split K
//    in half across 272 CTAs launched last -> tail wave at half duration.
//    Their out region is pre-initialized with bias in the conv launch
//    (8.5MB) and they RED-add partials (17MB) — costs ~3us vs R5's 176MB.
//  - Mainloop / mbarrier protocol / tile config: FROZEN (R7/R8 core).
// ============================================================================

#define DIM      2048
#define M_TOTAL  8192
#define BM       128
#define BN       128
#define BK       64
#define THREADS  256
#define STAGES   3
#define KITERS   (DIM / BK)          // 32

#define NTILE_X  (DIM / BN)          // 16
#define NTILES   ((M_TOTAL / BM) * NTILE_X)   // 1024
#define FULL_TILES 888               // 3 full waves of 296 (2 CTAs x 148 SM)
#define TAIL_TILES (NTILES - FULL_TILES)      // 136
#define GRID_TOTAL (FULL_TILES + 2 * TAIL_TILES)  // 1160

__device__ __half g_Xh[(size_t)M_TOTAL * DIM];   // 32 MB
__device__ __half g_Wh[(size_t)DIM * DIM];       //  8 MB

#define A_BYTES     16384
#define STAGE_BYTES 32768
#define TILES_BYTES (STAGES * STAGE_BYTES)       // 98304
#define SMEM_BYTES  (TILES_BYTES + 64)           // + mbarriers

// ---------------------------------------------------------------------------
__device__ __forceinline__ uint32_t smem_u32(const void* p) {
    uint32_t a;
    asm("{ .reg .u64 t; cvta.to.shared.u64 t, %1; cvt.u32.u64 %0, t; }"
        : "=r"(a) : "l"(p));
    return a;
}
__device__ __forceinline__ uint32_t swz(uint32_t b) {   // SW128
    return b ^ ((b >> 3) & 0x70);
}
__device__ __forceinline__ void cp16(uint32_t dst, const void* src) {
    asm volatile("cp.async.cg.shared.global [%0], [%1], 16;"
                 :: "r"(dst), "l"(src));
}
__device__ __forceinline__ void cp_arrive(uint32_t mbar) {
    asm volatile("cp.async.mbarrier.arrive.noinc.shared::cta.b64 [%0];"
                 :: "r"(mbar) : "memory");
}
__device__ __forceinline__ void mbar_init(uint32_t mbar, uint32_t cnt) {
    asm volatile("mbarrier.init.shared.b64 [%0], %1;" :: "r"(mbar), "r"(cnt) : "memory");
}
__device__ __forceinline__ void mbar_arrive(uint32_t mbar) {
    asm volatile("mbarrier.arrive.shared::cta.b64 _, [%0];" :: "r"(mbar) : "memory");
}
__device__ __forceinline__ void mbar_wait(uint32_t mbar, uint32_t parity) {
    asm volatile(
        "{\n\t.reg .pred P;\n\t"
        "WAITLP_%=:\n\t"
        "mbarrier.try_wait.parity.acquire.cta.shared::cta.b64 P, [%0], %1, 0x989680;\n\t"
        "@!P bra WAITLP_%=;\n\t}"
        :: "r"(mbar), "r"(parity) : "memory");
}
__device__ __forceinline__ void redf(float* p, float v) {
    asm volatile("red.global.add.f32 [%0], %1;" :: "l"(p), "f"(v) : "memory");
}

#define LDSM4(r0, r1, r2, r3, addr) \
    asm volatile("ldmatrix.sync.aligned.m8n8.x4.shared.b16 {%0,%1,%2,%3}, [%4];" \
                 : "=r"(r0), "=r"(r1), "=r"(r2), "=r"(r3) : "r"(addr))

#define MMA16816(c0, c1, c2, c3, a0, a1, a2, a3, b0, b1) \
    asm volatile("mma.sync.aligned.m16n8k16.row.col.f32.f16.f16.f32 " \
                 "{%0,%1,%2,%3}, {%4,%5,%6,%7}, {%8,%9}, {%0,%1,%2,%3};" \
                 : "+f"(c0), "+f"(c1), "+f"(c2), "+f"(c3) \
                 : "r"(a0), "r"(a1), "r"(a2), "r"(a3), "r"(b0), "r"(b1))

// ============================================================================
// prep: fp32 -> fp16 convert (8 floats/thread) + bias-init of tail-tile
// output region (tiles 888..1023), one launch
// ============================================================================
#define NX8 ((M_TOTAL * DIM) / 8)    // 2,097,152
#define NW8 ((DIM * DIM) / 8)        //   524,288
#define NT4 (TAIL_TILES * (BM * BN) / 4)     // 557,056
#define PREP_BLOCKS ((NX8 + NW8 + NT4) / 256)  // 12,416

__device__ __forceinline__ uint4 pack8(float4 v0, float4 v1) {
    __half2 h0 = __floats2half2_rn(v0.x, v0.y);
    __half2 h1 = __floats2half2_rn(v0.z, v0.w);
    __half2 h2 = __floats2half2_rn(v1.x, v1.y);
    __half2 h3 = __floats2half2_rn(v1.z, v1.w);
    uint4 p;
    p.x = *reinterpret_cast<uint32_t*>(&h0);
    p.y = *reinterpret_cast<uint32_t*>(&h1);
    p.z = *reinterpret_cast<uint32_t*>(&h2);
    p.w = *reinterpret_cast<uint32_t*>(&h3);
    return p;
}

__global__ void __launch_bounds__(256) prep_kernel(const float4* __restrict__ x,
                                                   const float4* __restrict__ W,
                                                   const float4* __restrict__ bias4,
                                                   float4* __restrict__ out4) {
    int i = blockIdx.x * 256 + threadIdx.x;
    if (i < NX8 + NW8) {
        const float4* src;
        uint4* dst;
        int j;
        if (i < NX8) { src = x; dst = reinterpret_cast<uint4*>(g_Xh); j = i; }
        else         { src = W; dst = reinterpret_cast<uint4*>(g_Wh); j = i - NX8; }
        float4 v0 = src[2 * j];
        float4 v1 = src[2 * j + 1];
        dst[j] = pack8(v0, v1);
    } else {
        // bias-init for tail tiles 888..1023
        int j = i - (NX8 + NW8);                 // [0, TAIL_TILES*4096)
        int tile = FULL_TILES + (j >> 12);       // 4096 float4 per tile
        int e = j & 4095;
        int r  = e >> 5;                         // row in tile (32 float4/row)
        int c4 = e & 31;
        int m_tile = tile >> 4;                  // /16
        int n_tile = tile & 15;
        int bidx = n_tile * 32 + c4;
        out4[(size_t)(m_tile * BM + r) * (DIM / 4) + bidx] = __ldg(&bias4[bidx]);
    }
}

// ============================================================================
// GEMM: 128x128 CTA tile, 8 warps (2Mx4N), warp tile 64x32, 3-stage mbarrier
// pipeline, 2 CTAs/SM. bid<888: full-K + store. bid>=888: half-K + RED.
// ============================================================================
struct Frag { uint32_t a[4][4]; uint32_t b[2][4]; };

__device__ __forceinline__ void ldsm_frags(Frag& f, uint32_t aB, uint32_t bB,
                                           uint32_t a_base, uint32_t b_base, int k16) {
    const uint32_t kb = (uint32_t)(k16 * 32);
    #pragma unroll
    for (int mt = 0; mt < 4; mt++) {
        uint32_t off = swz(a_base + kb) + (uint32_t)(mt << 11);
        LDSM4(f.a[mt][0], f.a[mt][1], f.a[mt][2], f.a[mt][3], aB + off);
    }
    #pragma unroll
    for (int p = 0; p < 2; p++) {
        uint32_t off = swz(b_base + kb) + (uint32_t)(p << 11);
        LDSM4(f.b[p][0], f.b[p][1], f.b[p][2], f.b[p][3], bB + off);
    }
}

__device__ __forceinline__ void mma_frags(float c[4][4][4], const Frag& f) {
    #pragma unroll
    for (int mt = 0; mt < 4; mt++)
        #pragma unroll
        for (int nb = 0; nb < 4; nb++)
            MMA16816(c[mt][nb][0], c[mt][nb][1], c[mt][nb][2], c[mt][nb][3],
                     f.a[mt][0], f.a[mt][1], f.a[mt][2], f.a[mt][3],
                     f.b[nb >> 1][(nb & 1) * 2], f.b[nb >> 1][(nb & 1) * 2 + 1]);
}

__global__ void __launch_bounds__(THREADS, 2) gemm_fp16_kernel(
    float* __restrict__ out, const float* __restrict__ bias)
{
    extern __shared__ __align__(1024) char smem[];
    const uint32_t sbase = smem_u32(smem);
    const int tid  = threadIdx.x;
    const int lane = tid & 31;
    const int wid  = tid >> 5;
    const int warp_m = wid & 1;
    const int warp_n = wid >> 1;
    const int bid  = blockIdx.x;

    // tile / K-range assignment
    int tile, kBase, iters;
    bool splitk;
    if (bid < FULL_TILES) {
        tile = bid;  kBase = 0;  iters = KITERS;  splitk = false;
    } else {
        int idx = bid - FULL_TILES;
        tile = FULL_TILES + (idx >> 1);
        kBase = (idx & 1) * (DIM / 2);
        iters = KITERS / 2;
        splitk = true;
    }
    const int mBase = (tile >> 4) * BM;   // tile/16
    const int nBase = (tile & 15) * BN;   // tile%16

    const uint32_t fullb  = sbase + TILES_BYTES;        // 3 x 8B
    const uint32_t emptyb = sbase + TILES_BYTES + 24;   // 3 x 8B

    if (tid == 0) {
        #pragma unroll
        for (int s = 0; s < STAGES; s++) {
            mbar_init(fullb  + s * 8, THREADS);   // each thread cp-arrives
            mbar_init(emptyb + s * 8, 8);         // one arrive per warp
        }
        // pre-trip empty[2]: its first producer wait (it=0) must pass
        #pragma unroll
        for (int k = 0; k < 8; k++) mbar_arrive(emptyb + 2 * 8);
    }

    // bias per thread (used by full tiles only)
    const int n0 = nBase + warp_n * 32 + (lane & 3) * 2;
    float2 bb[4];
    #pragma unroll
    for (int nb = 0; nb < 4; nb++)
        bb[nb] = __ldg(reinterpret_cast<const float2*>(bias + n0 + nb * 8));

    // per-thread cp.async bases
    const int ldr = tid >> 3;                 // 0..31
    const int ldc = (tid & 7) * 8;            // halves
    const __half* aSrc = g_Xh + (size_t)(mBase + ldr) * DIM + kBase + ldc;
    const __half* bSrc = g_Wh + (size_t)(nBase + ldr) * DIM + kBase + ldc;
    const uint32_t dOff = swz((uint32_t)(ldr * 128 + ldc * 2));

    float c[4][4][4];
    #pragma unroll
    for (int mt = 0; mt < 4; mt++)
        #pragma unroll
        for (int nb = 0; nb < 4; nb++)
            #pragma unroll
            for (int r = 0; r < 4; r++) c[mt][nb][r] = 0.0f;

    __syncthreads();   // mbarrier init visible before any use

    // prologue: produce chunks 0,1 into buffers 0,1
    #pragma unroll
    for (int s = 0; s < 2; s++) {
        const uint32_t st = sbase + (uint32_t)s * STAGE_BYTES;
        #pragma unroll
        for (int i = 0; i < 4; i++)
            cp16(st + dOff + (uint32_t)(i << 12), aSrc + (size_t)(i * 32) * DIM + s * BK);
        #pragma unroll
        for (int i = 0; i < 4; i++)
            cp16(st + A_BYTES + dOff + (uint32_t)(i << 12), bSrc + (size_t)(i * 32) * DIM + s * BK);
        cp_arrive(fullb + s * 8);
    }

    const uint32_t a_base = (uint32_t)(((warp_m * 64 + (lane & 15)) << 7) + ((lane >> 4) << 4));
    const uint32_t b_base = (uint32_t)(((warp_n * 32 + ((lane >> 4) << 3) + (lane & 7)) << 7)
                                       + (((lane >> 3) & 1) << 4));

    uint32_t pf = 0, pe = 0;   // per-stage parity bitmasks (bit s)
    int s = 0;
    Frag f0, f1;

    for (int it = 0; it < iters; ++it) {
        // ---- consume chunk it from buffer s ----
        mbar_wait(fullb + s * 8, (pf >> s) & 1u);
        pf ^= (1u << s);

        const uint32_t aB = sbase + (uint32_t)s * STAGE_BYTES;
        const uint32_t bB = aB + A_BYTES;

        ldsm_frags(f0, aB, bB, a_base, b_base, 0);
        ldsm_frags(f1, aB, bB, a_base, b_base, 1);
        mma_frags(c, f0);

        // ---- produce chunk it+2 into buffer sw ----
        if (it + 2 < iters) {
            int sw = s + 2; if (sw >= STAGES) sw -= STAGES;
            mbar_wait(emptyb + sw * 8, (pe >> sw) & 1u);
            pe ^= (1u << sw);

            const uint32_t st = sbase + (uint32_t)sw * STAGE_BYTES;
            const int kc = (it + 2) * BK;
            #pragma unroll
            for (int i = 0; i < 4; i++)
                cp16(st + dOff + (uint32_t)(i << 12), aSrc + (size_t)(i * 32) * DIM + kc);
            #pragma unroll
            for (int i = 0; i < 4; i++)
                cp16(st + A_BYTES + dOff + (uint32_t)(i << 12), bSrc + (size_t)(i * 32) * DIM + kc);
            cp_arrive(fullb + sw * 8);
        }

        ldsm_frags(f0, aB, bB, a_base, b_base, 2);
        mma_frags(c, f1);
        ldsm_frags(f1, aB, bB, a_base, b_base, 3);
        mma_frags(c, f0);
        mma_frags(c, f1);

        // all MMAs issued => all LDSM reads of buffer s completed
        if (lane == 0) mbar_arrive(emptyb + s * 8);

        s++; if (s == STAGES) s = 0;
    }

    // epilogue
    const int m0 = mBase + warp_m * 64 + (lane >> 2);
    if (!splitk) {
        #pragma unroll
        for (int mt = 0; mt < 4; mt++) {
            #pragma unroll
            for (int nb = 0; nb < 4; nb++) {
                const int row = m0 + mt * 16;
                const int col = n0 + nb * 8;
                float2 v0, v1;
                v0.x = c[mt][nb][0] + bb[nb].x;  v0.y = c[mt][nb][1] + bb[nb].y;
                v1.x = c[mt][nb][2] + bb[nb].x;  v1.y = c[mt][nb][3] + bb[nb].y;
                *reinterpret_cast<float2*>(out + (size_t)row * DIM + col) = v0;
                *reinterpret_cast<float2*>(out + (size_t)(row + 8) * DIM + col) = v1;
            }
        }
    } else {
        // out pre-initialized with bias in prep; add this half-K partial
        #pragma unroll
        for (int mt = 0; mt < 4; mt++) {
            #pragma unroll
            for (int nb = 0; nb < 4; nb++) {
                const int row = m0 + mt * 16;
                const int col = n0 + nb * 8;
                float* p0 = out + (size_t)row * DIM + col;
                float* p1 = out + (size_t)(row + 8) * DIM + col;
                redf(p0,     c[mt][nb][0]);
                redf(p0 + 1, c[mt][nb][1]);
                redf(p1,     c[mt][nb][2]);
                redf(p1 + 1, c[mt][nb][3]);
            }
        }
    }
}

// ============================================================================
// kernel_launch — graph-capturable, allocation-free
// ============================================================================
extern "C" void kernel_launch(void* const* d_in, const int* in_sizes, int n_in,
                              void* d_out, int out_size) {
    const float* x = (const float*)d_in[0];
    const float* W = (const float*)d_in[1];
    const float* b = (const float*)d_in[2];
    float* out = (float*)d_out;
    (void)in_sizes; (void)n_in; (void)out_size;

    prep_kernel<<<PREP_BLOCKS, 256>>>((const float4*)x, (const float4*)W,
                                      (const float4*)b, (float4*)out);

    cudaFuncSetAttribute(gemm_fp16_kernel,
                         cudaFuncAttributeMaxDynamicSharedMemorySize, SMEM_BYTES);
    gemm_fp16_kernel<<<GRID_TOTAL, THREADS, SMEM_BYTES>>>(out, b);
}